// round 7
// baseline (speedup 1.0000x reference)
#include <cuda_runtime.h>
#include <cuda_bf16.h>
#include <cstdint>
#include <cstring>

#define SEQ 4096
#define TQ  64
#define WIN 256
#define NB  4

// smem byte offsets: K-hi, K-lo, V-hi, V-lo (each 64 keys x 64 dims bf16 = 8KB)
#define KH 0
#define KL 8192
#define VH 16384
#define VL 24576

// key-split scratch: unnormalized O and l per half
__device__ float g_osc[2][(size_t)NB * SEQ * 64];
__device__ float g_lsc[2][NB * SEQ];

__device__ __forceinline__ uint32_t smem_u32(const void* p) {
    uint32_t a;
    asm("{ .reg .u64 t; cvta.to.shared.u64 t, %1; cvt.u32.u64 %0, t; }" : "=r"(a) : "l"(p));
    return a;
}
__device__ __forceinline__ float ex2(float x) {
    float r; asm("ex2.approx.ftz.f32 %0, %1;" : "=f"(r) : "f"(x)); return r;
}
__device__ __forceinline__ void ldsm4(uint32_t& r0, uint32_t& r1, uint32_t& r2, uint32_t& r3, uint32_t a) {
    asm volatile("ldmatrix.sync.aligned.m8n8.x4.shared.b16 {%0,%1,%2,%3}, [%4];"
                 : "=r"(r0), "=r"(r1), "=r"(r2), "=r"(r3) : "r"(a));
}
__device__ __forceinline__ void ldsm4t(uint32_t& r0, uint32_t& r1, uint32_t& r2, uint32_t& r3, uint32_t a) {
    asm volatile("ldmatrix.sync.aligned.m8n8.x4.trans.shared.b16 {%0,%1,%2,%3}, [%4];"
                 : "=r"(r0), "=r"(r1), "=r"(r2), "=r"(r3) : "r"(a));
}
__device__ __forceinline__ void mma4(float (&d)[4], uint32_t a0, uint32_t a1, uint32_t a2, uint32_t a3,
                                     uint32_t b0, uint32_t b1) {
    asm volatile("mma.sync.aligned.m16n8k16.row.col.f32.bf16.bf16.f32 "
                 "{%0,%1,%2,%3}, {%4,%5,%6,%7}, {%8,%9}, {%0,%1,%2,%3};"
                 : "+f"(d[0]), "+f"(d[1]), "+f"(d[2]), "+f"(d[3])
                 : "r"(a0), "r"(a1), "r"(a2), "r"(a3), "r"(b0), "r"(b1));
}
__device__ __forceinline__ uint32_t packbf(float x, float y) {
    __nv_bfloat162 v = __floats2bfloat162_rn(x, y);
    uint32_t u; memcpy(&u, &v, 4); return u;
}
__device__ __forceinline__ void splitp(float x, float y, uint32_t& h, uint32_t& l) {
    __nv_bfloat16 hx = __float2bfloat16(x), hy = __float2bfloat16(y);
    h = ((uint32_t)__bfloat16_as_ushort(hy) << 16) | __bfloat16_as_ushort(hx);
    l = packbf(x - __bfloat162float(hx), y - __bfloat162float(hy));
}

// MODE: 0 unmasked, 1 diagonal (valid j<=iq), 2 lowest (valid j>=iq-WIN)
template<int MODE>
__device__ __forceinline__ void do_tile(int k0, int tid, char* smc, uint32_t sbu,
                                        const float* __restrict__ qkv_b,
                                        const uint32_t (&qh)[4][4], const uint32_t (&ql)[4][4],
                                        float (&o)[8][4], float& l0acc, float& l1acc,
                                        int iq0, int iq1)
{
    const int lane = tid & 31, w = tid >> 5;
    const int t = lane & 3;
    const int rk = lane & 7;
    const uint32_t xorl = rk << 4;
    const uint32_t m16  = (lane >> 3) * 16;

    __syncthreads();   // previous tile fully consumed
    {   // convert K (threads 0-63) / V (threads 64-127) tile to bf16 hi/lo
        int r = tid & 63, isV = tid >> 6;
        const float4* src = reinterpret_cast<const float4*>(
            qkv_b + (size_t)(k0 + r) * 192 + 64 + isV * 64);
        char* hb = smc + (isV ? VH : KH) + r * 128;
        char* lb = smc + (isV ? VL : KL) + r * 128;
        uint32_t xr = (r & 7) << 4;
        #pragma unroll
        for (int gi = 0; gi < 8; gi++) {
            float4 f0 = src[2 * gi], f1 = src[2 * gi + 1];
            uint4 hv, lv;
            splitp(f0.x, f0.y, hv.x, lv.x);
            splitp(f0.z, f0.w, hv.y, lv.y);
            splitp(f1.x, f1.y, hv.z, lv.z);
            splitp(f1.z, f1.w, hv.w, lv.w);
            uint32_t off = (uint32_t)(gi * 16) ^ xr;
            *reinterpret_cast<uint4*>(hb + off) = hv;
            *reinterpret_cast<uint4*>(lb + off) = lv;
        }
    }
    __syncthreads();

    // ---- S = Q·K^T (split bf16: Qh*Kh + Ql*Kh + Qh*Kl) ----
    float s[8][4] = {};
    #pragma unroll
    for (int c = 0; c < 4; c += 2) {
        #pragma unroll
        for (int nt = 0; nt < 8; nt++) {
            if (MODE == 1 && nt >= 2 * w + 2) continue;   // fully above diagonal
            if (MODE == 2 && nt < 2 * w) continue;        // fully below window
            uint32_t base = sbu + (uint32_t)(nt * 1024 + rk * 128) + ((uint32_t)(c * 32 + m16) ^ xorl);
            uint32_t kh0, kh1, kh2, kh3, kl0, kl1, kl2, kl3;
            ldsm4(kh0, kh1, kh2, kh3, base + KH);
            ldsm4(kl0, kl1, kl2, kl3, base + KL);
            mma4(s[nt], qh[c][0], qh[c][1], qh[c][2], qh[c][3], kh0, kh1);
            mma4(s[nt], qh[c+1][0], qh[c+1][1], qh[c+1][2], qh[c+1][3], kh2, kh3);
            mma4(s[nt], ql[c][0], ql[c][1], ql[c][2], ql[c][3], kh0, kh1);
            mma4(s[nt], ql[c+1][0], ql[c+1][1], ql[c+1][2], ql[c+1][3], kh2, kh3);
            mma4(s[nt], qh[c][0], qh[c][1], qh[c][2], qh[c][3], kl0, kl1);
            mma4(s[nt], qh[c+1][0], qh[c+1][1], qh[c+1][2], qh[c+1][3], kl2, kl3);
        }
    }

    // ---- softmax (static max): p = valid ? 2^s : 0; split to bf16 hi/lo ----
    uint32_t ph[8], phB[8], pl[8], plB[8];
    #pragma unroll
    for (int nt = 0; nt < 8; nt++) {
        int j0 = k0 + nt * 8 + 2 * t, j1 = j0 + 1;
        bool v00 = true, v01 = true, v10 = true, v11 = true;
        if (MODE == 1) { v00 = j0 <= iq0; v01 = j1 <= iq0; v10 = j0 <= iq1; v11 = j1 <= iq1; }
        if (MODE == 2) { v00 = j0 >= iq0 - WIN; v01 = j1 >= iq0 - WIN;
                         v10 = j0 >= iq1 - WIN; v11 = j1 >= iq1 - WIN; }
        float p0 = v00 ? ex2(s[nt][0]) : 0.0f;
        float p1 = v01 ? ex2(s[nt][1]) : 0.0f;
        float p2 = v10 ? ex2(s[nt][2]) : 0.0f;
        float p3 = v11 ? ex2(s[nt][3]) : 0.0f;
        l0acc += p0 + p1;
        l1acc += p2 + p3;
        splitp(p0, p1, ph[nt], pl[nt]);
        splitp(p2, p3, phB[nt], plB[nt]);
    }

    // ---- O += P·V (split bf16: Ph*Vh + Pl*Vh + Ph*Vl), V via ldmatrix.trans ----
    const int matk = (lane >> 3) & 1, matn = lane >> 4;
    #pragma unroll
    for (int ck = 0; ck < 4; ck++) {
        if (MODE == 1 && ck > w) continue;
        if (MODE == 2 && ck < w) continue;
        uint32_t A0 = ph[2*ck], A1 = phB[2*ck], A2 = ph[2*ck+1], A3 = phB[2*ck+1];
        uint32_t L0 = pl[2*ck], L1 = plB[2*ck], L2 = pl[2*ck+1], L3 = plB[2*ck+1];
        uint32_t rowoff = (uint32_t)((ck * 16 + matk * 8 + rk) * 128);
        #pragma unroll
        for (int ntd = 0; ntd < 8; ntd += 2) {
            uint32_t base = sbu + rowoff + ((uint32_t)((ntd + matn) * 16) ^ xorl);
            uint32_t vh0, vh1, vh2, vh3, vl0, vl1, vl2, vl3;
            ldsm4t(vh0, vh1, vh2, vh3, base + VH);
            ldsm4t(vl0, vl1, vl2, vl3, base + VL);
            mma4(o[ntd],     A0, A1, A2, A3, vh0, vh1);
            mma4(o[ntd + 1], A0, A1, A2, A3, vh2, vh3);
            mma4(o[ntd],     L0, L1, L2, L3, vh0, vh1);
            mma4(o[ntd + 1], L0, L1, L2, L3, vh2, vh3);
            mma4(o[ntd],     A0, A1, A2, A3, vl0, vl1);
            mma4(o[ntd + 1], A0, A1, A2, A3, vl2, vl3);
        }
    }
}

__global__ __launch_bounds__(128, 3) void swa_mma(const float* __restrict__ qkv)
{
    __shared__ __align__(1024) char smc[32768];
    const uint32_t sbu = smem_u32(smc);
    const int tid = threadIdx.x, lane = tid & 31, w = tid >> 5;
    const int g = lane >> 2, t = lane & 3;
    const int b = blockIdx.y, q0 = blockIdx.x * TQ;
    const int z = blockIdx.z;                    // key-split half
    const float* qkv_b = qkv + (size_t)b * SEQ * 192;

    const int iq0 = q0 + w * 16 + g, iq1 = iq0 + 8;

    // ---- load Q fragments, scaled, split bf16 hi/lo ----
    const float SCL = 0.125f * 1.44269504088896f;   // 1/sqrt(64) * log2(e)
    uint32_t qh[4][4], ql[4][4];
    {
        const float* qp0 = qkv_b + (size_t)iq0 * 192;
        const float* qp1 = qkv_b + (size_t)iq1 * 192;
        #pragma unroll
        for (int c = 0; c < 4; c++) {
            float2 x0 = *reinterpret_cast<const float2*>(qp0 + c * 16 + 2 * t);
            float2 x1 = *reinterpret_cast<const float2*>(qp1 + c * 16 + 2 * t);
            float2 x2 = *reinterpret_cast<const float2*>(qp0 + c * 16 + 2 * t + 8);
            float2 x3 = *reinterpret_cast<const float2*>(qp1 + c * 16 + 2 * t + 8);
            splitp(x0.x * SCL, x0.y * SCL, qh[c][0], ql[c][0]);
            splitp(x1.x * SCL, x1.y * SCL, qh[c][1], ql[c][1]);
            splitp(x2.x * SCL, x2.y * SCL, qh[c][2], ql[c][2]);
            splitp(x3.x * SCL, x3.y * SCL, qh[c][3], ql[c][3]);
        }
    }

    float o[8][4] = {};
    float l0 = 0.0f, l1 = 0.0f;

    // Tile list: k0 = kstart + 64*i, i = 0..n-1; this CTA takes i%2 == z.
    const int kstart = q0 >= WIN ? q0 - WIN : 0;
    const int n = (q0 - kstart) / 64 + 1;
    for (int i = z; i < n; i += 2) {
        int k0 = kstart + 64 * i;
        if (q0 >= WIN && i == 0)
            do_tile<2>(k0, tid, smc, sbu, qkv_b, qh, ql, o, l0, l1, iq0, iq1);
        else if (k0 == q0)
            do_tile<1>(k0, tid, smc, sbu, qkv_b, qh, ql, o, l0, l1, iq0, iq1);
        else
            do_tile<0>(k0, tid, smc, sbu, qkv_b, qh, ql, o, l0, l1, iq0, iq1);
    }

    // ---- reduce l across the 4 lanes sharing a row; write partials ----
    l0 += __shfl_xor_sync(0xffffffffu, l0, 1);
    l0 += __shfl_xor_sync(0xffffffffu, l0, 2);
    l1 += __shfl_xor_sync(0xffffffffu, l1, 1);
    l1 += __shfl_xor_sync(0xffffffffu, l1, 2);
    if (t == 0) {
        g_lsc[z][b * SEQ + iq0] = l0;
        g_lsc[z][b * SEQ + iq1] = l1;
    }
    float* o0 = g_osc[z] + ((size_t)(b * SEQ + iq0)) * 64 + 2 * t;
    float* o1 = g_osc[z] + ((size_t)(b * SEQ + iq1)) * 64 + 2 * t;
    #pragma unroll
    for (int nt = 0; nt < 8; nt++) {
        *reinterpret_cast<float2*>(o0 + nt * 8) = make_float2(o[nt][0], o[nt][1]);
        *reinterpret_cast<float2*>(o1 + nt * 8) = make_float2(o[nt][2], o[nt][3]);
    }
}

__global__ __launch_bounds__(256) void swa_merge(float* __restrict__ out)
{
    int idx = blockIdx.x * 256 + threadIdx.x;     // one float4 (4 dims)
    int row = idx >> 4;                           // b*SEQ + s
    float rl = 1.0f / (g_lsc[0][row] + g_lsc[1][row]);
    float4 a = reinterpret_cast<const float4*>(g_osc[0])[idx];
    float4 c = reinterpret_cast<const float4*>(g_osc[1])[idx];
    reinterpret_cast<float4*>(out)[idx] =
        make_float4((a.x + c.x) * rl, (a.y + c.y) * rl,
                    (a.z + c.z) * rl, (a.w + c.w) * rl);
}

extern "C" void kernel_launch(void* const* d_in, const int* in_sizes, int n_in,
                              void* d_out, int out_size)
{
    const float* qkv = (const float*)d_in[0];
    float* out = (float*)d_out;
    int B = in_sizes[0] / (SEQ * 192);
    dim3 grid(SEQ / TQ, B, 2);
    swa_mma<<<grid, 128>>>(qkv);
    int nv4 = B * SEQ * 64 / 4;
    swa_merge<<<nv4 / 256, 256>>>(out);
}